// round 1
// baseline (speedup 1.0000x reference)
#include <cuda_runtime.h>
#include <math.h>

// Problem constants
#define NB 8
#define NT 2048
#define NC 1024
#define MTOT (NB * NT)          // 16384 rows total
#define EPSV 1e-6f

// ---------------------------------------------------------------------------
// Scratch (device globals — no allocation allowed in kernel_launch)
// ---------------------------------------------------------------------------
__device__ float g_h  [(size_t)MTOT * NC];        // rmsnorm output (reused for h2)
__device__ float g_qkv[(size_t)MTOT * 3 * NC];    // qkv projection
__device__ float g_sc [(size_t)NB * NT * NT];     // scores / attn (in-place softmax)
__device__ float g_av [(size_t)MTOT * NC];        // attn @ v
__device__ float g_x1 [(size_t)MTOT * NC];        // x + out-proj
__device__ float g_ff [(size_t)MTOT * 2 * NC];    // silu(h2 @ w1^T)

// ---------------------------------------------------------------------------
// f32x2 packed FMA helpers (sm_100+)
// ---------------------------------------------------------------------------
__device__ __forceinline__ unsigned long long pack_dup(float a) {
    unsigned long long r;
    asm("mov.b64 %0, {%1, %1};" : "=l"(r) : "f"(a));
    return r;
}
__device__ __forceinline__ void fma2(unsigned long long& d,
                                     unsigned long long a,
                                     unsigned long long b) {
    asm("fma.rn.f32x2 %0, %1, %2, %0;" : "+l"(d) : "l"(a), "l"(b));
}
__device__ __forceinline__ float2 unpack2(unsigned long long v) {
    float2 f;
    asm("mov.b64 {%0, %1}, %2;" : "=f"(f.x), "=f"(f.y) : "l"(v));
    return f;
}

// ---------------------------------------------------------------------------
// Block reductions (256 threads = 8 warps)
// ---------------------------------------------------------------------------
__device__ __forceinline__ float block_sum(float v) {
    #pragma unroll
    for (int o = 16; o > 0; o >>= 1) v += __shfl_xor_sync(0xffffffffu, v, o);
    __shared__ float sm[8];
    if ((threadIdx.x & 31) == 0) sm[threadIdx.x >> 5] = v;
    __syncthreads();
    float r = 0.f;
    #pragma unroll
    for (int i = 0; i < 8; i++) r += sm[i];
    __syncthreads();
    return r;
}
__device__ __forceinline__ float block_max(float v) {
    #pragma unroll
    for (int o = 16; o > 0; o >>= 1) v = fmaxf(v, __shfl_xor_sync(0xffffffffu, v, o));
    __shared__ float sm[8];
    if ((threadIdx.x & 31) == 0) sm[threadIdx.x >> 5] = v;
    __syncthreads();
    float r = -1e30f;
    #pragma unroll
    for (int i = 0; i < 8; i++) r = fmaxf(r, sm[i]);
    __syncthreads();
    return r;
}

// ---------------------------------------------------------------------------
// RMSNorm: one block per row of 1024 floats
// ---------------------------------------------------------------------------
__global__ __launch_bounds__(256) void rmsnorm_kernel(
    const float* __restrict__ x, const float* __restrict__ w,
    float* __restrict__ o)
{
    long long row = blockIdx.x;
    const float4* xr = (const float4*)(x + row * NC);
    float4 v = xr[threadIdx.x];
    float ss = v.x * v.x + v.y * v.y + v.z * v.z + v.w * v.w;
    ss = block_sum(ss);
    float scale = rsqrtf(ss * (1.f / NC) + EPSV);
    float4 wv = ((const float4*)w)[threadIdx.x];
    float4 r;
    r.x = v.x * scale * wv.x;
    r.y = v.y * scale * wv.y;
    r.z = v.z * scale * wv.z;
    r.w = v.w * scale * wv.w;
    ((float4*)(o + row * NC))[threadIdx.x] = r;
}

// ---------------------------------------------------------------------------
// GEMM NT:  C[M,N] = A[M,K] @ B[N,K]^T    (both K-contiguous)
// EPI: 0=plain, 1=*alpha, 2=silu, 3=+residual
// CSKIP: skip tiles fully above the causal diagonal (scores GEMM)
// Tiles: 128x128x16, 256 threads, 8x8 per thread, f32x2 FMAs.
// All dims assumed multiples of the tile sizes (true for this problem).
// ---------------------------------------------------------------------------
template<int EPI, bool CSKIP>
__global__ __launch_bounds__(256) void gemm_nt_kernel(
    const float* __restrict__ A, int lda, long long sA,
    const float* __restrict__ B, int ldb, long long sB,
    float* __restrict__ Cp, int ldc, long long sC,
    const float* __restrict__ R, long long sR,
    int K, float alpha)
{
    const int BM = 128, BN = 128, BK = 16;
    int rm = blockIdx.y * BM;
    int cn = blockIdx.x * BN;
    if (CSKIP && cn > rm + (BM - 1)) return;
    long long z = blockIdx.z;
    A  += z * sA;
    B  += z * sB;
    Cp += z * sC;
    if (EPI == 3) R += z * sR;

    __shared__ float As[BK][BM];
    __shared__ float Bs[BK][BN];

    int tid = threadIdx.x;
    int tx = tid & 15, ty = tid >> 4;
    int m0 = ty * 8, n0 = tx * 8;

    unsigned long long acc[8][4];
    #pragma unroll
    for (int i = 0; i < 8; i++)
        #pragma unroll
        for (int j = 0; j < 4; j++) acc[i][j] = 0ULL;

    for (int k0 = 0; k0 < K; k0 += BK) {
        #pragma unroll
        for (int i = 0; i < 2; i++) {
            int idx = tid + i * 256;
            int r = idx >> 2, c4 = (idx & 3) << 2;
            float4 va = *(const float4*)&A[(long long)(rm + r) * lda + k0 + c4];
            As[c4 + 0][r] = va.x; As[c4 + 1][r] = va.y;
            As[c4 + 2][r] = va.z; As[c4 + 3][r] = va.w;
            float4 vb = *(const float4*)&B[(long long)(cn + r) * ldb + k0 + c4];
            Bs[c4 + 0][r] = vb.x; Bs[c4 + 1][r] = vb.y;
            Bs[c4 + 2][r] = vb.z; Bs[c4 + 3][r] = vb.w;
        }
        __syncthreads();
        #pragma unroll
        for (int k = 0; k < BK; k++) {
            float4 a0 = *(const float4*)&As[k][m0];
            float4 a1 = *(const float4*)&As[k][m0 + 4];
            ulonglong2 b0 = *(const ulonglong2*)&Bs[k][n0];
            ulonglong2 b1 = *(const ulonglong2*)&Bs[k][n0 + 4];
            unsigned long long bv[4] = { b0.x, b0.y, b1.x, b1.y };
            float avv[8] = { a0.x, a0.y, a0.z, a0.w, a1.x, a1.y, a1.z, a1.w };
            #pragma unroll
            for (int i = 0; i < 8; i++) {
                unsigned long long ad = pack_dup(avv[i]);
                #pragma unroll
                for (int j = 0; j < 4; j++) fma2(acc[i][j], ad, bv[j]);
            }
        }
        __syncthreads();
    }

    #pragma unroll
    for (int i = 0; i < 8; i++) {
        long long row = rm + m0 + i;
        float out[8];
        #pragma unroll
        for (int j = 0; j < 4; j++) {
            float2 f = unpack2(acc[i][j]);
            out[2 * j] = f.x; out[2 * j + 1] = f.y;
        }
        if (EPI == 1) {
            #pragma unroll
            for (int j = 0; j < 8; j++) out[j] *= alpha;
        }
        if (EPI == 2) {
            #pragma unroll
            for (int j = 0; j < 8; j++) out[j] = out[j] / (1.f + __expf(-out[j]));
        }
        if (EPI == 3) {
            const float4* rr = (const float4*)&R[row * ldc + cn + n0];
            float4 r0 = rr[0], r1 = rr[1];
            out[0] += r0.x; out[1] += r0.y; out[2] += r0.z; out[3] += r0.w;
            out[4] += r1.x; out[5] += r1.y; out[6] += r1.z; out[7] += r1.w;
        }
        float4* cw = (float4*)&Cp[row * ldc + cn + n0];
        cw[0] = make_float4(out[0], out[1], out[2], out[3]);
        cw[1] = make_float4(out[4], out[5], out[6], out[7]);
    }
}

// ---------------------------------------------------------------------------
// GEMM NN:  C[M,N] = A[M,K] @ B[K,N]   (attn @ V); K clipped at the causal
// diagonal per row-tile (attn is zero above the diagonal).
// ---------------------------------------------------------------------------
__global__ __launch_bounds__(256) void gemm_nn_kernel(
    const float* __restrict__ A, int lda, long long sA,
    const float* __restrict__ B, int ldb, long long sB,
    float* __restrict__ Cp, int ldc, long long sC,
    int K)
{
    const int BM = 128, BN = 128, BK = 16;
    int rm = blockIdx.y * BM;
    int cn = blockIdx.x * BN;
    long long z = blockIdx.z;
    A  += z * sA;
    B  += z * sB;
    Cp += z * sC;

    int kend = min(K, rm + BM);   // causal: attn[t][s]==0 for s>t

    __shared__ float As[BK][BM];
    __shared__ float Bs[BK][BN];

    int tid = threadIdx.x;
    int tx = tid & 15, ty = tid >> 4;
    int m0 = ty * 8, n0 = tx * 8;

    unsigned long long acc[8][4];
    #pragma unroll
    for (int i = 0; i < 8; i++)
        #pragma unroll
        for (int j = 0; j < 4; j++) acc[i][j] = 0ULL;

    for (int k0 = 0; k0 < kend; k0 += BK) {
        #pragma unroll
        for (int i = 0; i < 2; i++) {
            int idx = tid + i * 256;
            // A: [BM x BK] K-contiguous -> transpose-on-store
            int r = idx >> 2, c4 = (idx & 3) << 2;
            float4 va = *(const float4*)&A[(long long)(rm + r) * lda + k0 + c4];
            As[c4 + 0][r] = va.x; As[c4 + 1][r] = va.y;
            As[c4 + 2][r] = va.z; As[c4 + 3][r] = va.w;
            // B: [BK x BN] N-contiguous -> direct store
            int br = idx >> 5, bc = (idx & 31) << 2;
            float4 vb = *(const float4*)&B[(long long)(k0 + br) * ldb + cn + bc];
            Bs[br][bc + 0] = vb.x; Bs[br][bc + 1] = vb.y;
            Bs[br][bc + 2] = vb.z; Bs[br][bc + 3] = vb.w;
        }
        __syncthreads();
        #pragma unroll
        for (int k = 0; k < BK; k++) {
            float4 a0 = *(const float4*)&As[k][m0];
            float4 a1 = *(const float4*)&As[k][m0 + 4];
            ulonglong2 b0 = *(const ulonglong2*)&Bs[k][n0];
            ulonglong2 b1 = *(const ulonglong2*)&Bs[k][n0 + 4];
            unsigned long long bv[4] = { b0.x, b0.y, b1.x, b1.y };
            float avv[8] = { a0.x, a0.y, a0.z, a0.w, a1.x, a1.y, a1.z, a1.w };
            #pragma unroll
            for (int i = 0; i < 8; i++) {
                unsigned long long ad = pack_dup(avv[i]);
                #pragma unroll
                for (int j = 0; j < 4; j++) fma2(acc[i][j], ad, bv[j]);
            }
        }
        __syncthreads();
    }

    #pragma unroll
    for (int i = 0; i < 8; i++) {
        long long row = rm + m0 + i;
        float4* cw = (float4*)&Cp[row * ldc + cn + n0];
        float2 f0 = unpack2(acc[i][0]), f1 = unpack2(acc[i][1]);
        float2 f2 = unpack2(acc[i][2]), f3 = unpack2(acc[i][3]);
        cw[0] = make_float4(f0.x, f0.y, f1.x, f1.y);
        cw[1] = make_float4(f2.x, f2.y, f3.x, f3.y);
    }
}

// ---------------------------------------------------------------------------
// Causal softmax, in place. One block per (b,t) row; zeros above diagonal.
// Scores are already scaled by alpha (done in the QK^T epilogue).
// ---------------------------------------------------------------------------
__global__ __launch_bounds__(256) void softmax_kernel(float* __restrict__ sc)
{
    long long row = blockIdx.x;                 // b*NT + t
    int t = (int)(row & (NT - 1));
    float* r = sc + row * NT;
    int n = t + 1;

    float v[8];
    float lmax = -1e30f;
    #pragma unroll
    for (int j = 0; j < 8; j++) {
        int i = threadIdx.x + j * 256;
        v[j] = (i < n) ? r[i] : -1e30f;
        lmax = fmaxf(lmax, v[j]);
    }
    float m = block_max(lmax);

    float lsum = 0.f;
    #pragma unroll
    for (int j = 0; j < 8; j++) {
        int i = threadIdx.x + j * 256;
        float e = (i < n) ? __expf(v[j] - m) : 0.f;
        v[j] = e;
        lsum += e;
    }
    float s = block_sum(lsum);
    float inv = 1.f / s;
    #pragma unroll
    for (int j = 0; j < 8; j++) {
        int i = threadIdx.x + j * 256;
        r[i] = v[j] * inv;                      // writes 0 for i >= n
    }
}

// ---------------------------------------------------------------------------
// Launch sequence
// ---------------------------------------------------------------------------
extern "C" void kernel_launch(void* const* d_in, const int* in_sizes, int n_in,
                              void* d_out, int out_size)
{
    const float* x     = (const float*)d_in[0];
    const float* ln1_w = (const float*)d_in[1];
    const float* ln2_w = (const float*)d_in[2];
    const float* qkv_w = (const float*)d_in[3];
    const float* out_w = (const float*)d_in[4];
    const float* w1    = (const float*)d_in[5];
    const float* w2    = (const float*)d_in[6];
    float* out = (float*)d_out;

    float *h_, *qkv_, *sc_, *av_, *x1_, *ff_;
    cudaGetSymbolAddress((void**)&h_,   g_h);
    cudaGetSymbolAddress((void**)&qkv_, g_qkv);
    cudaGetSymbolAddress((void**)&sc_,  g_sc);
    cudaGetSymbolAddress((void**)&av_,  g_av);
    cudaGetSymbolAddress((void**)&x1_,  g_x1);
    cudaGetSymbolAddress((void**)&ff_,  g_ff);

    const long long sQKV = (long long)NT * 3 * NC;   // per-batch stride in qkv
    const long long sSC  = (long long)NT * NT;       // per-batch stride in scores
    const long long sAV  = (long long)NT * NC;       // per-batch stride in av

    // 1. h = rmsnorm(x, ln1)
    rmsnorm_kernel<<<MTOT, 256>>>(x, ln1_w, h_);

    // 2. qkv = h @ qkv_w^T        [16384, 3072]
    gemm_nt_kernel<0, false><<<dim3(3 * NC / 128, MTOT / 128, 1), 256>>>(
        h_, NC, 0, qkv_w, NC, 0, qkv_, 3 * NC, 0, nullptr, 0, NC, 0.f);

    // 3. scores = (q @ k^T) * C^-0.5, causal tiles only   [8][2048,2048]
    gemm_nt_kernel<1, true><<<dim3(NT / 128, NT / 128, NB), 256>>>(
        qkv_,       3 * NC, sQKV,
        qkv_ + NC,  3 * NC, sQKV,
        sc_,        NT,     sSC,
        nullptr, 0, NC, 0.03125f /* 1/sqrt(1024) */);

    // 4. causal softmax in place
    softmax_kernel<<<MTOT, 256>>>(sc_);

    // 5. av = attn @ v   (K clipped at diagonal)   [8][2048,1024]
    gemm_nn_kernel<<<dim3(NC / 128, NT / 128, NB), 256>>>(
        sc_,            NT,     sSC,
        qkv_ + 2 * NC,  3 * NC, sQKV,
        av_,            NC,     sAV,
        NT);

    // 6. x1 = x + av @ out_w^T
    gemm_nt_kernel<3, false><<<dim3(NC / 128, MTOT / 128, 1), 256>>>(
        av_, NC, 0, out_w, NC, 0, x1_, NC, 0, x, 0, NC, 0.f);

    // 7. h2 = rmsnorm(x1, ln2)   (reuse g_h)
    rmsnorm_kernel<<<MTOT, 256>>>(x1_, ln2_w, h_);

    // 8. ff = silu(h2 @ w1^T)    [16384, 2048]
    gemm_nt_kernel<2, false><<<dim3(2 * NC / 128, MTOT / 128, 1), 256>>>(
        h_, NC, 0, w1, NC, 0, ff_, 2 * NC, 0, nullptr, 0, NC, 0.f);

    // 9. out = x1 + ff @ w2^T    [16384, 1024]
    gemm_nt_kernel<3, false><<<dim3(NC / 128, MTOT / 128, 1), 256>>>(
        ff_, 2 * NC, 0, w2, 2 * NC, 0, out, NC, 0, x1_, 0, 2 * NC, 0.f);
}

// round 3
// speedup vs baseline: 2.5888x; 2.5888x over previous
#include <cuda_runtime.h>
#include <cstdint>
#include <math.h>

#define NB 8
#define NT 2048
#define NC 1024
#define MTOT (NB * NT)
#define EPSV 1e-6f

// ---------------------------------------------------------------------------
// Scratch (device globals)
// ---------------------------------------------------------------------------
__device__ float g_h  [(size_t)MTOT * NC];
__device__ float g_qkv[(size_t)MTOT * 3 * NC];
__device__ float g_vt [(size_t)MTOT * NC];        // V transposed per batch [C][T]
__device__ float g_sc [(size_t)NB * NT * NT];
__device__ float g_av [(size_t)MTOT * NC];
__device__ float g_x1 [(size_t)MTOT * NC];
__device__ float g_ff [(size_t)MTOT * 2 * NC];

// ---------------------------------------------------------------------------
// Helpers
// ---------------------------------------------------------------------------
__device__ __forceinline__ uint32_t to_tf32(float x) {
    uint32_t r;
    asm("cvt.rna.tf32.f32 %0, %1;" : "=r"(r) : "f"(x));
    return r;
}
__device__ __forceinline__ void mma_tf32(float* c, const uint32_t* a, const uint32_t* b) {
    asm volatile(
        "mma.sync.aligned.m16n8k8.row.col.f32.tf32.tf32.f32 "
        "{%0,%1,%2,%3}, {%4,%5,%6,%7}, {%8,%9}, {%0,%1,%2,%3};"
        : "+f"(c[0]), "+f"(c[1]), "+f"(c[2]), "+f"(c[3])
        : "r"(a[0]), "r"(a[1]), "r"(a[2]), "r"(a[3]), "r"(b[0]), "r"(b[1]));
}

// ---------------------------------------------------------------------------
// tf32 mma.sync GEMM:  C[M,N] = A[M,K] @ B[N,K]^T   (both K-major fp32)
// CTA tile 128x128x32, 256 threads, warp tile 64x32, double-buffered smem.
// EPI: 0=plain, 1=*alpha, 2=silu, 3=+residual
// ---------------------------------------------------------------------------
template<int EPI, bool CSKIP, bool KCLIP>
__global__ __launch_bounds__(256) void gemm_mma(
    const float* __restrict__ A, int lda, long long sA,
    const float* __restrict__ B, int ldb, long long sB,
    float* __restrict__ C, int ldc, long long sC,
    const float* __restrict__ R, long long sR,
    int K, float alpha)
{
    constexpr int BM = 128, BN = 128, BK = 32;
    constexpr int TILE = BM * BK * 4;              // 16 KB (one operand, one stage)
    constexpr int STAGE = 2 * TILE;                // A + B per stage

    int rm = blockIdx.y * BM;
    int cn = blockIdx.x * BN;
    if (CSKIP && cn > rm) return;
    long long z = blockIdx.z;
    A += z * sA; B += z * sB; C += z * sC;
    if (EPI == 3) R += z * sR;

    int kend = KCLIP ? min(K, rm + BM) : K;
    int nk = kend / BK;

    extern __shared__ char smem[];                 // 2 stages * 32KB

    int tid  = threadIdx.x;
    int lane = tid & 31;
    int warp = tid >> 5;
    int wm0 = (warp & 1) * 64;                     // warp row offset
    int wn0 = (warp >> 1) * 32;                    // warp col offset
    int grp = lane >> 2;                           // 0..7
    int q   = lane & 3;                            // 0..3

    // producer mapping: 4 x 16B chunks per thread per operand tile
    // chunk id = tid + t*256 ; row = id>>3 ; g = id&7
    // swizzled sts offset: row*128 + ((g*16) ^ ((row&7)<<4))
    int prow[4], psts[4];
    #pragma unroll
    for (int t = 0; t < 4; t++) {
        int id = tid + t * 256;
        int row = id >> 3, g = id & 7;
        prow[t] = row;
        psts[t] = row * 128 + ((g * 16) ^ ((row & 7) << 4));
    }
    const int pg4 = (tid & 7) * 4;                 // gmem float offset within k-block

    float c[4][4][4];
    #pragma unroll
    for (int i = 0; i < 4; i++)
        #pragma unroll
        for (int j = 0; j < 4; j++)
            #pragma unroll
            for (int e = 0; e < 4; e++) c[i][j][e] = 0.f;

    // ---- prologue: stage 0 ----
    {
        char* sa = smem;
        char* sb = smem + TILE;
        #pragma unroll
        for (int t = 0; t < 4; t++) {
            float4 va = *(const float4*)&A[(long long)(rm + prow[t]) * lda + pg4];
            *(uint4*)(sa + psts[t]) =
                make_uint4(to_tf32(va.x), to_tf32(va.y), to_tf32(va.z), to_tf32(va.w));
            float4 vb = *(const float4*)&B[(long long)(cn + prow[t]) * ldb + pg4];
            *(uint4*)(sb + psts[t]) =
                make_uint4(to_tf32(vb.x), to_tf32(vb.y), to_tf32(vb.z), to_tf32(vb.w));
        }
    }
    __syncthreads();

    const int xm = grp << 4;                       // XOR mask (same for A and B frags)

    for (int ki = 0; ki < nk; ki++) {
        // prefetch next k-block to registers
        float4 pa[4], pb[4];
        bool pf = (ki + 1) < nk;
        if (pf) {
            int k0g = (ki + 1) * BK + pg4;
            #pragma unroll
            for (int t = 0; t < 4; t++) {
                pa[t] = *(const float4*)&A[(long long)(rm + prow[t]) * lda + k0g];
                pb[t] = *(const float4*)&B[(long long)(cn + prow[t]) * ldb + k0g];
            }
        }

        // compute on current stage
        char* sa = smem + (ki & 1) * STAGE;
        char* sb = sa + TILE;
        #pragma unroll
        for (int ks = 0; ks < 4; ks++) {
            int k0 = ks * 8;
            int ka = ((k0 + q) * 4) ^ xm;          // byte offset of frag col 0
            int kb = ((k0 + q + 4) * 4) ^ xm;      // byte offset of frag col 1
            uint32_t af[4][4], bf[4][2];
            #pragma unroll
            for (int i = 0; i < 4; i++) {
                int mb = (wm0 + i * 16 + grp) * 128;
                af[i][0] = *(const uint32_t*)(sa + mb + ka);
                af[i][1] = *(const uint32_t*)(sa + mb + 1024 + ka);   // +8 rows
                af[i][2] = *(const uint32_t*)(sa + mb + kb);
                af[i][3] = *(const uint32_t*)(sa + mb + 1024 + kb);
            }
            #pragma unroll
            for (int j = 0; j < 4; j++) {
                int nb = (wn0 + j * 8 + grp) * 128;
                bf[j][0] = *(const uint32_t*)(sb + nb + ka);
                bf[j][1] = *(const uint32_t*)(sb + nb + kb);
            }
            #pragma unroll
            for (int i = 0; i < 4; i++)
                #pragma unroll
                for (int j = 0; j < 4; j++)
                    mma_tf32(c[i][j], af[i], bf[j]);
        }
        __syncthreads();

        // store prefetched block into the other stage
        if (pf) {
            char* da = smem + ((ki + 1) & 1) * STAGE;
            char* db = da + TILE;
            #pragma unroll
            for (int t = 0; t < 4; t++) {
                *(uint4*)(da + psts[t]) =
                    make_uint4(to_tf32(pa[t].x), to_tf32(pa[t].y), to_tf32(pa[t].z), to_tf32(pa[t].w));
                *(uint4*)(db + psts[t]) =
                    make_uint4(to_tf32(pb[t].x), to_tf32(pb[t].y), to_tf32(pb[t].z), to_tf32(pb[t].w));
            }
            __syncthreads();
        }
    }

    // ---- epilogue ----
    #pragma unroll
    for (int i = 0; i < 4; i++) {
        int r0 = rm + wm0 + i * 16 + grp;
        #pragma unroll
        for (int j = 0; j < 4; j++) {
            int c0 = cn + wn0 + j * 8 + 2 * q;
            float v[4] = { c[i][j][0], c[i][j][1], c[i][j][2], c[i][j][3] };
            if (EPI == 1) {
                #pragma unroll
                for (int e = 0; e < 4; e++) v[e] *= alpha;
            }
            if (EPI == 2) {
                #pragma unroll
                for (int e = 0; e < 4; e++) v[e] = v[e] / (1.f + __expf(-v[e]));
            }
            if (EPI == 3) {
                float2 r0v = *(const float2*)&R[(long long)r0 * ldc + c0];
                float2 r1v = *(const float2*)&R[(long long)(r0 + 8) * ldc + c0];
                v[0] += r0v.x; v[1] += r0v.y; v[2] += r1v.x; v[3] += r1v.y;
            }
            *(float2*)&C[(long long)r0 * ldc + c0]       = make_float2(v[0], v[1]);
            *(float2*)&C[(long long)(r0 + 8) * ldc + c0] = make_float2(v[2], v[3]);
        }
    }
}

// ---------------------------------------------------------------------------
// Block reductions (256 threads)
// ---------------------------------------------------------------------------
__device__ __forceinline__ float block_sum(float v) {
    #pragma unroll
    for (int o = 16; o > 0; o >>= 1) v += __shfl_xor_sync(0xffffffffu, v, o);
    __shared__ float sm[8];
    if ((threadIdx.x & 31) == 0) sm[threadIdx.x >> 5] = v;
    __syncthreads();
    float r = 0.f;
    #pragma unroll
    for (int i = 0; i < 8; i++) r += sm[i];
    __syncthreads();
    return r;
}
__device__ __forceinline__ float block_max(float v) {
    #pragma unroll
    for (int o = 16; o > 0; o >>= 1) v = fmaxf(v, __shfl_xor_sync(0xffffffffu, v, o));
    __shared__ float sm[8];
    if ((threadIdx.x & 31) == 0) sm[threadIdx.x >> 5] = v;
    __syncthreads();
    float r = -1e30f;
    #pragma unroll
    for (int i = 0; i < 8; i++) r = fmaxf(r, sm[i]);
    __syncthreads();
    return r;
}

// ---------------------------------------------------------------------------
// RMSNorm
// ---------------------------------------------------------------------------
__global__ __launch_bounds__(256) void rmsnorm_kernel(
    const float* __restrict__ x, const float* __restrict__ w, float* __restrict__ o)
{
    long long row = blockIdx.x;
    float4 v = ((const float4*)(x + row * NC))[threadIdx.x];
    float ss = v.x * v.x + v.y * v.y + v.z * v.z + v.w * v.w;
    ss = block_sum(ss);
    float scale = rsqrtf(ss * (1.f / NC) + EPSV);
    float4 wv = ((const float4*)w)[threadIdx.x];
    float4 r;
    r.x = v.x * scale * wv.x; r.y = v.y * scale * wv.y;
    r.z = v.z * scale * wv.z; r.w = v.w * scale * wv.w;
    ((float4*)(o + row * NC))[threadIdx.x] = r;
}

// ---------------------------------------------------------------------------
// Causal softmax in place
// ---------------------------------------------------------------------------
__global__ __launch_bounds__(256) void softmax_kernel(float* __restrict__ sc)
{
    long long row = blockIdx.x;
    int t = (int)(row & (NT - 1));
    float* r = sc + row * NT;
    int n = t + 1;
    float v[8];
    float lmax = -1e30f;
    #pragma unroll
    for (int j = 0; j < 8; j++) {
        int i = threadIdx.x + j * 256;
        v[j] = (i < n) ? r[i] : -1e30f;
        lmax = fmaxf(lmax, v[j]);
    }
    float m = block_max(lmax);
    float lsum = 0.f;
    #pragma unroll
    for (int j = 0; j < 8; j++) {
        int i = threadIdx.x + j * 256;
        float e = (i < n) ? __expf(v[j] - m) : 0.f;
        v[j] = e;
        lsum += e;
    }
    float s = block_sum(lsum);
    float inv = 1.f / s;
    #pragma unroll
    for (int j = 0; j < 8; j++) {
        int i = threadIdx.x + j * 256;
        r[i] = v[j] * inv;
    }
}

// ---------------------------------------------------------------------------
// Transpose V: qkv[b][s][2C..3C] -> vt[b][c][s]
// ---------------------------------------------------------------------------
__global__ __launch_bounds__(256) void transpose_v_kernel(
    const float* __restrict__ qkv, float* __restrict__ vt)
{
    __shared__ float tile[32][33];
    int b = blockIdx.z;
    int s0 = blockIdx.x * 32, c0 = blockIdx.y * 32;
    const float* V = qkv + (long long)b * NT * 3 * NC + 2 * NC;
    float* VT = vt + (long long)b * NT * NC;
    int tx = threadIdx.x & 31, ty = threadIdx.x >> 5;
    #pragma unroll
    for (int k = 0; k < 32; k += 8)
        tile[ty + k][tx] = V[(long long)(s0 + ty + k) * (3 * NC) + c0 + tx];
    __syncthreads();
    #pragma unroll
    for (int k = 0; k < 32; k += 8)
        VT[(long long)(c0 + ty + k) * NT + s0 + tx] = tile[tx][ty + k];
}

// ---------------------------------------------------------------------------
// Launch sequence
// ---------------------------------------------------------------------------
extern "C" void kernel_launch(void* const* d_in, const int* in_sizes, int n_in,
                              void* d_out, int out_size)
{
    const float* x     = (const float*)d_in[0];
    const float* ln1_w = (const float*)d_in[1];
    const float* ln2_w = (const float*)d_in[2];
    const float* qkv_w = (const float*)d_in[3];
    const float* out_w = (const float*)d_in[4];
    const float* w1    = (const float*)d_in[5];
    const float* w2    = (const float*)d_in[6];
    float* out = (float*)d_out;

    float *h_, *qkv_, *vt_, *sc_, *av_, *x1_, *ff_;
    cudaGetSymbolAddress((void**)&h_,   g_h);
    cudaGetSymbolAddress((void**)&qkv_, g_qkv);
    cudaGetSymbolAddress((void**)&vt_,  g_vt);
    cudaGetSymbolAddress((void**)&sc_,  g_sc);
    cudaGetSymbolAddress((void**)&av_,  g_av);
    cudaGetSymbolAddress((void**)&x1_,  g_x1);
    cudaGetSymbolAddress((void**)&ff_,  g_ff);

    const long long sQKV = (long long)NT * 3 * NC;
    const long long sSC  = (long long)NT * NT;
    const long long sAV  = (long long)NT * NC;

    const int SMEM = 2 * 2 * 128 * 32 * 4;   // 64 KB

    {
        typedef void (*gfn)(const float*, int, long long, const float*, int, long long,
                            float*, int, long long, const float*, long long, int, float);
        gfn fs[5] = { gemm_mma<0, false, false>, gemm_mma<1, true, false>,
                      gemm_mma<0, false, true>,  gemm_mma<3, false, false>,
                      gemm_mma<2, false, false> };
        for (int i = 0; i < 5; i++)
            cudaFuncSetAttribute((const void*)fs[i],
                                 cudaFuncAttributeMaxDynamicSharedMemorySize, SMEM);
    }

    // 1. h = rmsnorm(x, ln1)
    rmsnorm_kernel<<<MTOT, 256>>>(x, ln1_w, h_);

    // 2. qkv = h @ qkv_w^T   [16384, 3072]
    gemm_mma<0, false, false><<<dim3(3 * NC / 128, MTOT / 128, 1), 256, SMEM>>>(
        h_, NC, 0, qkv_w, NC, 0, qkv_, 3 * NC, 0, nullptr, 0, NC, 0.f);

    // 3. vt = transpose(V)
    transpose_v_kernel<<<dim3(NT / 32, NC / 32, NB), 256>>>(qkv_, vt_);

    // 4. scores = (q @ k^T) / 32, causal tiles only
    gemm_mma<1, true, false><<<dim3(NT / 128, NT / 128, NB), 256, SMEM>>>(
        qkv_, 3 * NC, sQKV, qkv_ + NC, 3 * NC, sQKV,
        sc_, NT, sSC, nullptr, 0, NC, 0.03125f);

    // 5. causal softmax in place
    softmax_kernel<<<MTOT, 256>>>(sc_);

    // 6. av = attn @ vt^T (K clipped at diagonal)
    gemm_mma<0, false, true><<<dim3(NC / 128, NT / 128, NB), 256, SMEM>>>(
        sc_, NT, sSC, vt_, NT, sAV,
        av_, NC, sAV, nullptr, 0, NT, 0.f);

    // 7. x1 = x + av @ out_w^T
    gemm_mma<3, false, false><<<dim3(NC / 128, MTOT / 128, 1), 256, SMEM>>>(
        av_, NC, 0, out_w, NC, 0, x1_, NC, 0, x, 0, NC, 0.f);

    // 8. h2 = rmsnorm(x1, ln2)
    rmsnorm_kernel<<<MTOT, 256>>>(x1_, ln2_w, h_);

    // 9. ff = silu(h2 @ w1^T)   [16384, 2048]
    gemm_mma<2, false, false><<<dim3(2 * NC / 128, MTOT / 128, 1), 256, SMEM>>>(
        h_, NC, 0, w1, NC, 0, ff_, 2 * NC, 0, nullptr, 0, NC, 0.f);

    // 10. out = x1 + ff @ w2^T
    gemm_mma<3, false, false><<<dim3(NC / 128, MTOT / 128, 1), 256, SMEM>>>(
        ff_, 2 * NC, 0, w2, 2 * NC, 0, out, NC, 0, x1_, 0, 2 * NC, 0.f);
}

// round 4
// speedup vs baseline: 3.9105x; 1.5105x over previous
#include <cuda_runtime.h>
#include <cstdint>
#include <math.h>

#define NB 8
#define NT 2048
#define NC 1024
#define MTOT (NB * NT)
#define EPSV 1e-6f

// ---------------------------------------------------------------------------
// Scratch (device globals)
// ---------------------------------------------------------------------------
__device__ float g_h  [(size_t)MTOT * NC];
__device__ float g_qkv[(size_t)MTOT * 3 * NC];
__device__ float g_vt [(size_t)MTOT * NC];        // V transposed per batch [C][T]
__device__ float g_sc [(size_t)NB * NT * NT];
__device__ float g_av [(size_t)MTOT * NC];
__device__ float g_x1 [(size_t)MTOT * NC];
__device__ float g_ff [(size_t)MTOT * 2 * NC];
__device__ float g_w  [(size_t)8 * NC * NC];      // tf32-rounded weights

// ---------------------------------------------------------------------------
// Helpers
// ---------------------------------------------------------------------------
__device__ __forceinline__ uint32_t to_tf32(float x) {
    uint32_t r;
    asm("cvt.rna.tf32.f32 %0, %1;" : "=r"(r) : "f"(x));
    return r;
}
__device__ __forceinline__ float rnd_tf32(float x) {
    return __uint_as_float(to_tf32(x));
}
__device__ __forceinline__ uint32_t smem_u32(const void* p) {
    uint32_t a;
    asm("{ .reg .u64 t; cvta.to.shared.u64 t, %1; cvt.u32.u64 %0, t; }"
        : "=r"(a) : "l"(p));
    return a;
}
__device__ __forceinline__ void cp_async16(uint32_t dst_smem, const void* src) {
    asm volatile("cp.async.cg.shared.global [%0], [%1], 16;"
                 :: "r"(dst_smem), "l"(src) : "memory");
}
__device__ __forceinline__ void cp_commit() {
    asm volatile("cp.async.commit_group;" ::: "memory");
}
template<int N>
__device__ __forceinline__ void cp_wait() {
    asm volatile("cp.async.wait_group %0;" :: "n"(N) : "memory");
}
__device__ __forceinline__ void mma_tf32(float* c, const uint32_t* a, const uint32_t* b) {
    asm volatile(
        "mma.sync.aligned.m16n8k8.row.col.f32.tf32.tf32.f32 "
        "{%0,%1,%2,%3}, {%4,%5,%6,%7}, {%8,%9}, {%0,%1,%2,%3};"
        : "+f"(c[0]), "+f"(c[1]), "+f"(c[2]), "+f"(c[3])
        : "r"(a[0]), "r"(a[1]), "r"(a[2]), "r"(a[3]), "r"(b[0]), "r"(b[1]));
}

// ---------------------------------------------------------------------------
// tf32 mma.sync GEMM:  C[M,N] = A[M,K] @ B[N,K]^T   (both K-major fp32,
// values already tf32-rounded). CTA 128x128x32, 256 threads, warp 64x32,
// 3-stage cp.async pipeline.  EPI: 0=plain, 1=*alpha, 2=silu, 3=+residual
// ROUND: round outputs to tf32 (for buffers consumed by later GEMMs)
// ---------------------------------------------------------------------------
template<int EPI, bool CSKIP, bool KCLIP, bool ROUND>
__global__ __launch_bounds__(256, 2) void gemm_mma(
    const float* __restrict__ A, int lda, long long sA,
    const float* __restrict__ B, int ldb, long long sB,
    float* __restrict__ C, int ldc, long long sC,
    const float* __restrict__ R, long long sR,
    int K, float alpha)
{
    constexpr int BM = 128, BN = 128, BK = 32;
    constexpr int TILE = BM * BK * 4;              // 16 KB
    constexpr int STAGE = 2 * TILE;                // 32 KB
    constexpr int S = 3;

    int rm = blockIdx.y * BM;
    int cn = blockIdx.x * BN;
    if (CSKIP && cn > rm) return;
    long long z = blockIdx.z;
    A += z * sA; B += z * sB; C += z * sC;
    if (EPI == 3) R += z * sR;

    int kend = KCLIP ? min(K, rm + BM) : K;
    int nk = kend / BK;

    extern __shared__ char smem[];                 // 3 stages * 32KB
    uint32_t smem_base = smem_u32(smem);

    int tid  = threadIdx.x;
    int lane = tid & 31;
    int warp = tid >> 5;
    int wm0 = (warp & 1) * 64;
    int wn0 = (warp >> 1) * 32;
    int grp = lane >> 2;
    int q   = lane & 3;

    // producer mapping: 4 x 16B chunks per thread per operand tile
    int prow[4], psts[4];
    #pragma unroll
    for (int t = 0; t < 4; t++) {
        int id = tid + t * 256;
        int row = id >> 3, g = id & 7;
        prow[t] = row;
        psts[t] = row * 128 + ((g * 16) ^ ((row & 7) << 4));
    }
    const int pg4 = (tid & 7) * 4;

    float c[4][4][4];
    #pragma unroll
    for (int i = 0; i < 4; i++)
        #pragma unroll
        for (int j = 0; j < 4; j++)
            #pragma unroll
            for (int e = 0; e < 4; e++) c[i][j][e] = 0.f;

    // ---- prologue: stages 0..S-2 ----
    #pragma unroll
    for (int s = 0; s < S - 1; s++) {
        if (s < nk) {
            uint32_t sa = smem_base + s * STAGE;
            int k0 = s * BK + pg4;
            #pragma unroll
            for (int t = 0; t < 4; t++) {
                cp_async16(sa + psts[t],        &A[(long long)(rm + prow[t]) * lda + k0]);
                cp_async16(sa + TILE + psts[t], &B[(long long)(cn + prow[t]) * ldb + k0]);
            }
        }
        cp_commit();
    }

    const int xm = grp << 4;

    for (int ki = 0; ki < nk; ki++) {
        cp_wait<S - 2>();
        __syncthreads();

        // issue stage ki+S-1 (overwrites slot consumed in iteration ki-1)
        if (ki + S - 1 < nk) {
            int kn = ki + S - 1;
            uint32_t sa = smem_base + (kn % S) * STAGE;
            int k0 = kn * BK + pg4;
            #pragma unroll
            for (int t = 0; t < 4; t++) {
                cp_async16(sa + psts[t],        &A[(long long)(rm + prow[t]) * lda + k0]);
                cp_async16(sa + TILE + psts[t], &B[(long long)(cn + prow[t]) * ldb + k0]);
            }
        }
        cp_commit();

        // compute stage ki%S
        char* sa = smem + (ki % S) * STAGE;
        char* sb = sa + TILE;
        #pragma unroll
        for (int ks = 0; ks < 4; ks++) {
            int k0 = ks * 8;
            int ka = ((k0 + q) * 4) ^ xm;
            int kb = ((k0 + q + 4) * 4) ^ xm;
            uint32_t af[4][4], bf[4][2];
            #pragma unroll
            for (int i = 0; i < 4; i++) {
                int mb = (wm0 + i * 16 + grp) * 128;
                af[i][0] = *(const uint32_t*)(sa + mb + ka);
                af[i][1] = *(const uint32_t*)(sa + mb + 1024 + ka);
                af[i][2] = *(const uint32_t*)(sa + mb + kb);
                af[i][3] = *(const uint32_t*)(sa + mb + 1024 + kb);
            }
            #pragma unroll
            for (int j = 0; j < 4; j++) {
                int nb = (wn0 + j * 8 + grp) * 128;
                bf[j][0] = *(const uint32_t*)(sb + nb + ka);
                bf[j][1] = *(const uint32_t*)(sb + nb + kb);
            }
            #pragma unroll
            for (int i = 0; i < 4; i++)
                #pragma unroll
                for (int j = 0; j < 4; j++)
                    mma_tf32(c[i][j], af[i], bf[j]);
        }
        __syncthreads();
    }

    // ---- epilogue ----
    #pragma unroll
    for (int i = 0; i < 4; i++) {
        int r0 = rm + wm0 + i * 16 + grp;
        #pragma unroll
        for (int j = 0; j < 4; j++) {
            int c0 = cn + wn0 + j * 8 + 2 * q;
            float v[4] = { c[i][j][0], c[i][j][1], c[i][j][2], c[i][j][3] };
            if (EPI == 1) {
                #pragma unroll
                for (int e = 0; e < 4; e++) v[e] *= alpha;
            }
            if (EPI == 2) {
                #pragma unroll
                for (int e = 0; e < 4; e++) v[e] = v[e] / (1.f + __expf(-v[e]));
            }
            if (EPI == 3) {
                float2 r0v = *(const float2*)&R[(long long)r0 * ldc + c0];
                float2 r1v = *(const float2*)&R[(long long)(r0 + 8) * ldc + c0];
                v[0] += r0v.x; v[1] += r0v.y; v[2] += r1v.x; v[3] += r1v.y;
            }
            if (ROUND) {
                #pragma unroll
                for (int e = 0; e < 4; e++) v[e] = rnd_tf32(v[e]);
            }
            *(float2*)&C[(long long)r0 * ldc + c0]       = make_float2(v[0], v[1]);
            *(float2*)&C[(long long)(r0 + 8) * ldc + c0] = make_float2(v[2], v[3]);
        }
    }
}

// ---------------------------------------------------------------------------
// Block reductions (256 threads)
// ---------------------------------------------------------------------------
__device__ __forceinline__ float block_sum(float v) {
    #pragma unroll
    for (int o = 16; o > 0; o >>= 1) v += __shfl_xor_sync(0xffffffffu, v, o);
    __shared__ float sm[8];
    if ((threadIdx.x & 31) == 0) sm[threadIdx.x >> 5] = v;
    __syncthreads();
    float r = 0.f;
    #pragma unroll
    for (int i = 0; i < 8; i++) r += sm[i];
    __syncthreads();
    return r;
}
__device__ __forceinline__ float block_max(float v) {
    #pragma unroll
    for (int o = 16; o > 0; o >>= 1) v = fmaxf(v, __shfl_xor_sync(0xffffffffu, v, o));
    __shared__ float sm[8];
    if ((threadIdx.x & 31) == 0) sm[threadIdx.x >> 5] = v;
    __syncthreads();
    float r = -1e30f;
    #pragma unroll
    for (int i = 0; i < 8; i++) r = fmaxf(r, sm[i]);
    __syncthreads();
    return r;
}

// ---------------------------------------------------------------------------
// RMSNorm (output tf32-rounded; consumed only by GEMMs)
// ---------------------------------------------------------------------------
__global__ __launch_bounds__(256) void rmsnorm_kernel(
    const float* __restrict__ x, const float* __restrict__ w, float* __restrict__ o)
{
    long long row = blockIdx.x;
    float4 v = ((const float4*)(x + row * NC))[threadIdx.x];
    float ss = v.x * v.x + v.y * v.y + v.z * v.z + v.w * v.w;
    ss = block_sum(ss);
    float scale = rsqrtf(ss * (1.f / NC) + EPSV);
    float4 wv = ((const float4*)w)[threadIdx.x];
    float4 r;
    r.x = rnd_tf32(v.x * scale * wv.x); r.y = rnd_tf32(v.y * scale * wv.y);
    r.z = rnd_tf32(v.z * scale * wv.z); r.w = rnd_tf32(v.w * scale * wv.w);
    ((float4*)(o + row * NC))[threadIdx.x] = r;
}

// ---------------------------------------------------------------------------
// Causal softmax in place (output tf32-rounded; consumed by av GEMM)
// ---------------------------------------------------------------------------
__global__ __launch_bounds__(256) void softmax_kernel(float* __restrict__ sc)
{
    long long row = blockIdx.x;
    int t = (int)(row & (NT - 1));
    float* r = sc + row * NT;
    int n = t + 1;
    float v[8];
    float lmax = -1e30f;
    #pragma unroll
    for (int j = 0; j < 8; j++) {
        int i = threadIdx.x + j * 256;
        v[j] = (i < n) ? r[i] : -1e30f;
        lmax = fmaxf(lmax, v[j]);
    }
    float m = block_max(lmax);
    float lsum = 0.f;
    #pragma unroll
    for (int j = 0; j < 8; j++) {
        int i = threadIdx.x + j * 256;
        float e = (i < n) ? __expf(v[j] - m) : 0.f;
        v[j] = e;
        lsum += e;
    }
    float s = block_sum(lsum);
    float inv = 1.f / s;
    #pragma unroll
    for (int j = 0; j < 8; j++) {
        int i = threadIdx.x + j * 256;
        r[i] = rnd_tf32(v[j] * inv);
    }
}

// ---------------------------------------------------------------------------
// Transpose V (values already rounded by qkv GEMM epilogue)
// ---------------------------------------------------------------------------
__global__ __launch_bounds__(256) void transpose_v_kernel(
    const float* __restrict__ qkv, float* __restrict__ vt)
{
    __shared__ float tile[32][33];
    int b = blockIdx.z;
    int s0 = blockIdx.x * 32, c0 = blockIdx.y * 32;
    const float* V = qkv + (long long)b * NT * 3 * NC + 2 * NC;
    float* VT = vt + (long long)b * NT * NC;
    int tx = threadIdx.x & 31, ty = threadIdx.x >> 5;
    #pragma unroll
    for (int k = 0; k < 32; k += 8)
        tile[ty + k][tx] = V[(long long)(s0 + ty + k) * (3 * NC) + c0 + tx];
    __syncthreads();
    #pragma unroll
    for (int k = 0; k < 32; k += 8)
        VT[(long long)(c0 + ty + k) * NT + s0 + tx] = tile[tx][ty + k];
}

// ---------------------------------------------------------------------------
// Weight tf32 rounding pass
// ---------------------------------------------------------------------------
__global__ __launch_bounds__(256) void cvt_tf32_kernel(
    const float* __restrict__ src, float* __restrict__ dst)
{
    long long i = ((long long)blockIdx.x * 256 + threadIdx.x) * 4;
    float4 v = *(const float4*)(src + i);
    *(uint4*)(dst + i) = make_uint4(to_tf32(v.x), to_tf32(v.y), to_tf32(v.z), to_tf32(v.w));
}

// ---------------------------------------------------------------------------
// Launch sequence
// ---------------------------------------------------------------------------
extern "C" void kernel_launch(void* const* d_in, const int* in_sizes, int n_in,
                              void* d_out, int out_size)
{
    const float* x     = (const float*)d_in[0];
    const float* ln1_w = (const float*)d_in[1];
    const float* ln2_w = (const float*)d_in[2];
    const float* qkv_w = (const float*)d_in[3];
    const float* out_w = (const float*)d_in[4];
    const float* w1    = (const float*)d_in[5];
    const float* w2    = (const float*)d_in[6];
    float* out = (float*)d_out;

    float *h_, *qkv_, *vt_, *sc_, *av_, *x1_, *ff_, *w_;
    cudaGetSymbolAddress((void**)&h_,   g_h);
    cudaGetSymbolAddress((void**)&qkv_, g_qkv);
    cudaGetSymbolAddress((void**)&vt_,  g_vt);
    cudaGetSymbolAddress((void**)&sc_,  g_sc);
    cudaGetSymbolAddress((void**)&av_,  g_av);
    cudaGetSymbolAddress((void**)&x1_,  g_x1);
    cudaGetSymbolAddress((void**)&ff_,  g_ff);
    cudaGetSymbolAddress((void**)&w_,   g_w);

    float* qkv_wt = w_;                       // 3C*C
    float* out_wt = w_ + (size_t)3 * NC * NC; // C*C
    float* w1t    = w_ + (size_t)4 * NC * NC; // 2C*C
    float* w2t    = w_ + (size_t)6 * NC * NC; // 2C*C

    const long long sQKV = (long long)NT * 3 * NC;
    const long long sSC  = (long long)NT * NT;
    const long long sAV  = (long long)NT * NC;

    const int SMEM = 3 * 2 * 128 * 32 * 4;    // 96 KB

    {
        typedef void (*gfn)(const float*, int, long long, const float*, int, long long,
                            float*, int, long long, const float*, long long, int, float);
        gfn fs[6] = { gemm_mma<0, false, false, true>,  gemm_mma<1, true, false, false>,
                      gemm_mma<0, false, true,  true>,  gemm_mma<3, false, false, false>,
                      gemm_mma<2, false, false, true>,  gemm_mma<3, false, false, false> };
        for (int i = 0; i < 5; i++)
            cudaFuncSetAttribute((const void*)fs[i],
                                 cudaFuncAttributeMaxDynamicSharedMemorySize, SMEM);
    }

    // 0. round weights to tf32
    cvt_tf32_kernel<<<3 * NC * NC / 1024, 256>>>(qkv_w, qkv_wt);
    cvt_tf32_kernel<<<NC * NC / 1024,     256>>>(out_w, out_wt);
    cvt_tf32_kernel<<<2 * NC * NC / 1024, 256>>>(w1, w1t);
    cvt_tf32_kernel<<<2 * NC * NC / 1024, 256>>>(w2, w2t);

    // 1. h = rmsnorm(x, ln1)  (tf32-rounded)
    rmsnorm_kernel<<<MTOT, 256>>>(x, ln1_w, h_);

    // 2. qkv = h @ qkv_w^T   [16384, 3072]  (rounded)
    gemm_mma<0, false, false, true><<<dim3(3 * NC / 128, MTOT / 128, 1), 256, SMEM>>>(
        h_, NC, 0, qkv_wt, NC, 0, qkv_, 3 * NC, 0, nullptr, 0, NC, 0.f);

    // 3. vt = transpose(V)
    transpose_v_kernel<<<dim3(NT / 32, NC / 32, NB), 256>>>(qkv_, vt_);

    // 4. scores = (q @ k^T) / 32, causal tiles only
    gemm_mma<1, true, false, false><<<dim3(NT / 128, NT / 128, NB), 256, SMEM>>>(
        qkv_, 3 * NC, sQKV, qkv_ + NC, 3 * NC, sQKV,
        sc_, NT, sSC, nullptr, 0, NC, 0.03125f);

    // 5. causal softmax in place (rounded)
    softmax_kernel<<<MTOT, 256>>>(sc_);

    // 6. av = attn @ vt^T (K clipped at diagonal, rounded)
    gemm_mma<0, false, true, true><<<dim3(NC / 128, NT / 128, NB), 256, SMEM>>>(
        sc_, NT, sSC, vt_, NT, sAV,
        av_, NC, sAV, nullptr, 0, NT, 0.f);

    // 7. x1 = x + av @ out_w^T  (exact fp32)
    gemm_mma<3, false, false, false><<<dim3(NC / 128, MTOT / 128, 1), 256, SMEM>>>(
        av_, NC, 0, out_wt, NC, 0, x1_, NC, 0, x, 0, NC, 0.f);

    // 8. h2 = rmsnorm(x1, ln2)  (rounded)
    rmsnorm_kernel<<<MTOT, 256>>>(x1_, ln2_w, h_);

    // 9. ff = silu(h2 @ w1^T)   [16384, 2048]  (rounded)
    gemm_mma<2, false, false, true><<<dim3(2 * NC / 128, MTOT / 128, 1), 256, SMEM>>>(
        h_, NC, 0, w1t, NC, 0, ff_, 2 * NC, 0, nullptr, 0, NC, 0.f);

    // 10. out = x1 + ff @ w2^T  (exact fp32)
    gemm_mma<3, false, false, false><<<dim3(NC / 128, MTOT / 128, 1), 256, SMEM>>>(
        ff_, 2 * NC, 0, w2t, 2 * NC, 0, out, NC, 0, x1_, 0, 2 * NC, 0.f);
}

// round 6
// speedup vs baseline: 7.0794x; 1.8103x over previous
#include <cuda_runtime.h>
#include <cuda_fp16.h>
#include <cstdint>
#include <math.h>

#define NB 8
#define NT 2048
#define NC 1024
#define MTOT (NB * NT)
#define EPSV 1e-6f

typedef __half fp16;
typedef __half2 fp162;

// ---------------------------------------------------------------------------
// Scratch (device globals)
// ---------------------------------------------------------------------------
__device__ __align__(16) fp16  g_h  [(size_t)MTOT * NC];
__device__ __align__(16) fp16  g_qkv[(size_t)MTOT * 3 * NC];
__device__ __align__(16) fp16  g_vt [(size_t)MTOT * NC];     // V^T per batch [C][T]
__device__ __align__(16) fp16  g_sc [(size_t)NB * NT * NT];  // scores / attn
__device__ __align__(16) fp16  g_av [(size_t)MTOT * NC];
__device__ __align__(16) float g_x1 [(size_t)MTOT * NC];     // residual stream (fp32)
__device__ __align__(16) fp16  g_ff [(size_t)MTOT * 2 * NC];
__device__ __align__(16) fp16  g_wh [(size_t)8 * NC * NC];   // fp16 weights

// ---------------------------------------------------------------------------
// Helpers
// ---------------------------------------------------------------------------
__device__ __forceinline__ uint32_t smem_u32(const void* p) {
    uint32_t a;
    asm("{ .reg .u64 t; cvta.to.shared.u64 t, %1; cvt.u32.u64 %0, t; }"
        : "=r"(a) : "l"(p));
    return a;
}
__device__ __forceinline__ void cp_async16(uint32_t dst_smem, const void* src) {
    asm volatile("cp.async.cg.shared.global [%0], [%1], 16;"
                 :: "r"(dst_smem), "l"(src) : "memory");
}
__device__ __forceinline__ void cp_commit() {
    asm volatile("cp.async.commit_group;" ::: "memory");
}
template<int N>
__device__ __forceinline__ void cp_wait() {
    asm volatile("cp.async.wait_group %0;" :: "n"(N) : "memory");
}
__device__ __forceinline__ void mma_f16(float* c, const uint32_t* a, const uint32_t* b) {
    asm volatile(
        "mma.sync.aligned.m16n8k16.row.col.f32.f16.f16.f32 "
        "{%0,%1,%2,%3}, {%4,%5,%6,%7}, {%8,%9}, {%0,%1,%2,%3};"
        : "+f"(c[0]), "+f"(c[1]), "+f"(c[2]), "+f"(c[3])
        : "r"(a[0]), "r"(a[1]), "r"(a[2]), "r"(a[3]), "r"(b[0]), "r"(b[1]));
}

// ---------------------------------------------------------------------------
// fp16 mma.sync GEMM:  C[M,N] = A[M,K] @ B[N,K]^T  (A,B fp16 K-major)
// CTA 128x128x64(elems), 256 threads, warp 64x32, 3-stage cp.async pipeline.
// EPI: 0=plain, 1=*alpha, 2=silu, 3=+residual(fp32)
// TC:  output type (fp16 or float)
// ---------------------------------------------------------------------------
template<int EPI, bool CSKIP, bool KCLIP, typename TC>
__global__ __launch_bounds__(256, 2) void gemm_hf(
    const fp16* __restrict__ A, int lda, long long sA,
    const fp16* __restrict__ B, int ldb, long long sB,
    TC* __restrict__ C, int ldc, long long sC,
    const float* __restrict__ R, long long sR,
    int K, float alpha)
{
    constexpr int BM = 128, BK = 64;               // BK in elements (128 bytes)
    constexpr int TILE = BM * 128;                 // 16 KB per operand per stage
    constexpr int STAGE = 2 * TILE;                // 32 KB
    constexpr int S = 3;

    int rm = blockIdx.y * BM;
    int cn = blockIdx.x * BM;
    if (CSKIP && cn > rm) return;
    long long z = blockIdx.z;
    A += z * sA; B += z * sB; C += z * sC;
    if (EPI == 3) R += z * sR;

    int kend = KCLIP ? min(K, rm + BM) : K;
    int nk = kend / BK;

    extern __shared__ char smem[];                 // 3 * 32 KB
    uint32_t smem_base = smem_u32(smem);

    int tid  = threadIdx.x;
    int lane = tid & 31;
    int warp = tid >> 5;
    int wm0 = (warp & 1) * 64;
    int wn0 = (warp >> 1) * 32;
    int grp = lane >> 2;
    int q   = lane & 3;

    // producer: 4 x 16B chunks per thread per operand tile (128 rows x 128B)
    int prow[4], psts[4];
    #pragma unroll
    for (int t = 0; t < 4; t++) {
        int id = tid + t * 256;
        int row = id >> 3, g = id & 7;
        prow[t] = row;
        psts[t] = row * 128 + ((g * 16) ^ ((row & 7) << 4));
    }
    const int pg = (tid & 7) * 8;                  // element offset within k-block

    float c[4][4][4];
    #pragma unroll
    for (int i = 0; i < 4; i++)
        #pragma unroll
        for (int j = 0; j < 4; j++)
            #pragma unroll
            for (int e = 0; e < 4; e++) c[i][j][e] = 0.f;

    #pragma unroll
    for (int s = 0; s < S - 1; s++) {
        if (s < nk) {
            uint32_t sa = smem_base + s * STAGE;
            int k0 = s * BK + pg;
            #pragma unroll
            for (int t = 0; t < 4; t++) {
                cp_async16(sa + psts[t],        &A[(long long)(rm + prow[t]) * lda + k0]);
                cp_async16(sa + TILE + psts[t], &B[(long long)(cn + prow[t]) * ldb + k0]);
            }
        }
        cp_commit();
    }

    const int xm = grp << 4;

    for (int ki = 0; ki < nk; ki++) {
        cp_wait<S - 2>();
        __syncthreads();

        if (ki + S - 1 < nk) {
            int kn = ki + S - 1;
            uint32_t sa = smem_base + (kn % S) * STAGE;
            int k0 = kn * BK + pg;
            #pragma unroll
            for (int t = 0; t < 4; t++) {
                cp_async16(sa + psts[t],        &A[(long long)(rm + prow[t]) * lda + k0]);
                cp_async16(sa + TILE + psts[t], &B[(long long)(cn + prow[t]) * ldb + k0]);
            }
        }
        cp_commit();

        char* sa = smem + (ki % S) * STAGE;
        char* sb = sa + TILE;
        #pragma unroll
        for (int ks = 0; ks < 4; ks++) {           // 4 x k16 = 64 elements
            int ka = (ks * 32 + 4 * q) ^ xm;       // bytes: cols 2q,2q+1
            int kb = (ks * 32 + 16 + 4 * q) ^ xm;  // bytes: cols 2q+8,2q+9
            uint32_t af[4][4], bf[4][2];
            #pragma unroll
            for (int i = 0; i < 4; i++) {
                int mb = (wm0 + i * 16 + grp) * 128;
                af[i][0] = *(const uint32_t*)(sa + mb + ka);
                af[i][1] = *(const uint32_t*)(sa + mb + 1024 + ka);
                af[i][2] = *(const uint32_t*)(sa + mb + kb);
                af[i][3] = *(const uint32_t*)(sa + mb + 1024 + kb);
            }
            #pragma unroll
            for (int j = 0; j < 4; j++) {
                int nb = (wn0 + j * 8 + grp) * 128;
                bf[j][0] = *(const uint32_t*)(sb + nb + ka);
                bf[j][1] = *(const uint32_t*)(sb + nb + kb);
            }
            #pragma unroll
            for (int i = 0; i < 4; i++)
                #pragma unroll
                for (int j = 0; j < 4; j++)
                    mma_f16(c[i][j], af[i], bf[j]);
        }
        __syncthreads();
    }

    // ---- epilogue ----
    #pragma unroll
    for (int i = 0; i < 4; i++) {
        int r0 = rm + wm0 + i * 16 + grp;
        #pragma unroll
        for (int j = 0; j < 4; j++) {
            int c0 = cn + wn0 + j * 8 + 2 * q;
            float v[4] = { c[i][j][0], c[i][j][1], c[i][j][2], c[i][j][3] };
            if (EPI == 1) {
                #pragma unroll
                for (int e = 0; e < 4; e++) v[e] *= alpha;
            }
            if (EPI == 2) {
                #pragma unroll
                for (int e = 0; e < 4; e++) v[e] = v[e] / (1.f + __expf(-v[e]));
            }
            if (EPI == 3) {
                float2 r0v = *(const float2*)&R[(long long)r0 * ldc + c0];
                float2 r1v = *(const float2*)&R[(long long)(r0 + 8) * ldc + c0];
                v[0] += r0v.x; v[1] += r0v.y; v[2] += r1v.x; v[3] += r1v.y;
            }
            if (sizeof(TC) == 2) {
                fp162* p0 = (fp162*)&C[(long long)r0 * ldc + c0];
                fp162* p1 = (fp162*)&C[(long long)(r0 + 8) * ldc + c0];
                *p0 = __floats2half2_rn(v[0], v[1]);
                *p1 = __floats2half2_rn(v[2], v[3]);
            } else {
                *(float2*)&C[(long long)r0 * ldc + c0]       = make_float2(v[0], v[1]);
                *(float2*)&C[(long long)(r0 + 8) * ldc + c0] = make_float2(v[2], v[3]);
            }
        }
    }
}

// ---------------------------------------------------------------------------
// Block reductions (256 threads)
// ---------------------------------------------------------------------------
__device__ __forceinline__ float block_sum(float v) {
    #pragma unroll
    for (int o = 16; o > 0; o >>= 1) v += __shfl_xor_sync(0xffffffffu, v, o);
    __shared__ float sm[8];
    if ((threadIdx.x & 31) == 0) sm[threadIdx.x >> 5] = v;
    __syncthreads();
    float r = 0.f;
    #pragma unroll
    for (int i = 0; i < 8; i++) r += sm[i];
    __syncthreads();
    return r;
}
__device__ __forceinline__ float block_max(float v) {
    #pragma unroll
    for (int o = 16; o > 0; o >>= 1) v = fmaxf(v, __shfl_xor_sync(0xffffffffu, v, o));
    __shared__ float sm[8];
    if ((threadIdx.x & 31) == 0) sm[threadIdx.x >> 5] = v;
    __syncthreads();
    float r = -1e30f;
    #pragma unroll
    for (int i = 0; i < 8; i++) r = fmaxf(r, sm[i]);
    __syncthreads();
    return r;
}

// ---------------------------------------------------------------------------
// RMSNorm: fp32 in -> fp16 out
// ---------------------------------------------------------------------------
__global__ __launch_bounds__(256) void rmsnorm_kernel(
    const float* __restrict__ x, const float* __restrict__ w, fp16* __restrict__ o)
{
    long long row = blockIdx.x;
    float4 v = ((const float4*)(x + row * NC))[threadIdx.x];
    float ss = v.x * v.x + v.y * v.y + v.z * v.z + v.w * v.w;
    ss = block_sum(ss);
    float scale = rsqrtf(ss * (1.f / NC) + EPSV);
    float4 wv = ((const float4*)w)[threadIdx.x];
    fp162 a = __floats2half2_rn(v.x * scale * wv.x, v.y * scale * wv.y);
    fp162 b = __floats2half2_rn(v.z * scale * wv.z, v.w * scale * wv.w);
    uint2 pk = make_uint2(*(uint32_t*)&a, *(uint32_t*)&b);
    ((uint2*)(o + row * NC))[threadIdx.x] = pk;
}

// ---------------------------------------------------------------------------
// Causal softmax in place (fp16 in/out, fp32 math)
// ---------------------------------------------------------------------------
__global__ __launch_bounds__(256) void softmax_kernel(fp16* __restrict__ sc)
{
    long long row = blockIdx.x;
    int t = (int)(row & (NT - 1));
    fp16* r = sc + row * NT;
    int n = t + 1;
    int base = threadIdx.x * 8;

    uint4 raw = ((const uint4*)r)[threadIdx.x];
    float v[8];
    {
        uint32_t rw[4] = { raw.x, raw.y, raw.z, raw.w };
        #pragma unroll
        for (int p = 0; p < 4; p++) {
            float2 f = __half22float2(*(fp162*)&rw[p]);
            v[2 * p] = f.x; v[2 * p + 1] = f.y;
        }
    }
    float lmax = -1e30f;
    #pragma unroll
    for (int e = 0; e < 8; e++) {
        if (base + e >= n) v[e] = -1e30f;
        lmax = fmaxf(lmax, v[e]);
    }
    float m = block_max(lmax);
    float lsum = 0.f;
    #pragma unroll
    for (int e = 0; e < 8; e++) {
        float ex = (base + e < n) ? __expf(v[e] - m) : 0.f;
        v[e] = ex;
        lsum += ex;
    }
    float s = block_sum(lsum);
    float inv = 1.f / s;
    uint32_t ow[4];
    #pragma unroll
    for (int p = 0; p < 4; p++) {
        fp162 pk = __floats2half2_rn(v[2 * p] * inv, v[2 * p + 1] * inv);
        ow[p] = *(uint32_t*)&pk;
    }
    ((uint4*)r)[threadIdx.x] = make_uint4(ow[0], ow[1], ow[2], ow[3]);
}

// ---------------------------------------------------------------------------
// Transpose V: qkv[b][s][2C..3C] -> vt[b][c][s]   (fp16)
// ---------------------------------------------------------------------------
__global__ __launch_bounds__(256) void transpose_v_kernel(
    const fp16* __restrict__ qkv, fp16* __restrict__ vt)
{
    __shared__ fp16 tile[32][34];
    int b = blockIdx.z;
    int s0 = blockIdx.x * 32, c0 = blockIdx.y * 32;
    const fp16* V = qkv + (long long)b * NT * 3 * NC + 2 * NC;
    fp16* VT = vt + (long long)b * NT * NC;
    int tx = threadIdx.x & 31, ty = threadIdx.x >> 5;
    #pragma unroll
    for (int k = 0; k < 32; k += 8)
        tile[ty + k][tx] = V[(long long)(s0 + ty + k) * (3 * NC) + c0 + tx];
    __syncthreads();
    #pragma unroll
    for (int k = 0; k < 32; k += 8)
        VT[(long long)(c0 + ty + k) * NT + s0 + tx] = tile[tx][ty + k];
}

// ---------------------------------------------------------------------------
// Weight fp32 -> fp16 conversion (8 elems/thread)
// ---------------------------------------------------------------------------
__global__ __launch_bounds__(256) void cvt_w_kernel(
    const float* __restrict__ src, fp16* __restrict__ dst)
{
    long long i = ((long long)blockIdx.x * 256 + threadIdx.x) * 8;
    float4 v0 = *(const float4*)(src + i);
    float4 v1 = *(const float4*)(src + i + 4);
    fp162 p0 = __floats2half2_rn(v0.x, v0.y);
    fp162 p1 = __floats2half2_rn(v0.z, v0.w);
    fp162 p2 = __floats2half2_rn(v1.x, v1.y);
    fp162 p3 = __floats2half2_rn(v1.z, v1.w);
    *(uint4*)(dst + i) = make_uint4(*(uint32_t*)&p0, *(uint32_t*)&p1,
                                    *(uint32_t*)&p2, *(uint32_t*)&p3);
}

// ---------------------------------------------------------------------------
// Launch sequence
// ---------------------------------------------------------------------------
extern "C" void kernel_launch(void* const* d_in, const int* in_sizes, int n_in,
                              void* d_out, int out_size)
{
    const float* x     = (const float*)d_in[0];
    const float* ln1_w = (const float*)d_in[1];
    const float* ln2_w = (const float*)d_in[2];
    const float* qkv_w = (const float*)d_in[3];
    const float* out_w = (const float*)d_in[4];
    const float* w1    = (const float*)d_in[5];
    const float* w2    = (const float*)d_in[6];
    float* out = (float*)d_out;

    fp16 *h_, *qkv_, *vt_, *sc_, *av_, *ff_, *wh_;
    float* x1_;
    cudaGetSymbolAddress((void**)&h_,   g_h);
    cudaGetSymbolAddress((void**)&qkv_, g_qkv);
    cudaGetSymbolAddress((void**)&vt_,  g_vt);
    cudaGetSymbolAddress((void**)&sc_,  g_sc);
    cudaGetSymbolAddress((void**)&av_,  g_av);
    cudaGetSymbolAddress((void**)&x1_,  g_x1);
    cudaGetSymbolAddress((void**)&ff_,  g_ff);
    cudaGetSymbolAddress((void**)&wh_,  g_wh);

    fp16* qkv_wh = wh_;                        // 3C*C
    fp16* out_wh = wh_ + (size_t)3 * NC * NC;  // C*C
    fp16* w1h    = wh_ + (size_t)4 * NC * NC;  // 2C*C
    fp16* w2h    = wh_ + (size_t)6 * NC * NC;  // 2C*C

    const long long sQKV = (long long)NT * 3 * NC;
    const long long sSC  = (long long)NT * NT;
    const long long sAV  = (long long)NT * NC;

    const int SMEM = 3 * 2 * 128 * 128;        // 96 KB

    {
        cudaFuncSetAttribute((const void*)gemm_hf<0, false, false, fp16>,
                             cudaFuncAttributeMaxDynamicSharedMemorySize, SMEM);
        cudaFuncSetAttribute((const void*)gemm_hf<1, true, false, fp16>,
                             cudaFuncAttributeMaxDynamicSharedMemorySize, SMEM);
        cudaFuncSetAttribute((const void*)gemm_hf<0, false, true, fp16>,
                             cudaFuncAttributeMaxDynamicSharedMemorySize, SMEM);
        cudaFuncSetAttribute((const void*)gemm_hf<3, false, false, float>,
                             cudaFuncAttributeMaxDynamicSharedMemorySize, SMEM);
        cudaFuncSetAttribute((const void*)gemm_hf<2, false, false, fp16>,
                             cudaFuncAttributeMaxDynamicSharedMemorySize, SMEM);
    }

    // 0. weights -> fp16
    cvt_w_kernel<<<3 * NC * NC / 2048, 256>>>(qkv_w, qkv_wh);
    cvt_w_kernel<<<NC * NC / 2048,     256>>>(out_w, out_wh);
    cvt_w_kernel<<<2 * NC * NC / 2048, 256>>>(w1, w1h);
    cvt_w_kernel<<<2 * NC * NC / 2048, 256>>>(w2, w2h);

    // 1. h = rmsnorm(x, ln1)  (fp16)
    rmsnorm_kernel<<<MTOT, 256>>>(x, ln1_w, h_);

    // 2. qkv = h @ qkv_w^T   [16384, 3072] fp16
    gemm_hf<0, false, false, fp16><<<dim3(3 * NC / 128, MTOT / 128, 1), 256, SMEM>>>(
        h_, NC, 0, qkv_wh, NC, 0, qkv_, 3 * NC, 0, nullptr, 0, NC, 0.f);

    // 3. vt = transpose(V)
    transpose_v_kernel<<<dim3(NT / 32, NC / 32, NB), 256>>>(qkv_, vt_);

    // 4. scores = (q @ k^T) / 32, causal tiles only
    gemm_hf<1, true, false, fp16><<<dim3(NT / 128, NT / 128, NB), 256, SMEM>>>(
        qkv_, 3 * NC, sQKV, qkv_ + NC, 3 * NC, sQKV,
        sc_, NT, sSC, nullptr, 0, NC, 0.03125f);

    // 5. causal softmax in place
    softmax_kernel<<<MTOT, 256>>>(sc_);

    // 6. av = attn @ vt^T (K clipped at diagonal)
    gemm_hf<0, false, true, fp16><<<dim3(NC / 128, NT / 128, NB), 256, SMEM>>>(
        sc_, NT, sSC, vt_, NT, sAV,
        av_, NC, sAV, nullptr, 0, NT, 0.f);

    // 7. x1 = x + av @ out_w^T  (fp32 out)
    gemm_hf<3, false, false, float><<<dim3(NC / 128, MTOT / 128, 1), 256, SMEM>>>(
        av_, NC, 0, out_wh, NC, 0, x1_, NC, 0, x, 0, NC, 0.f);

    // 8. h2 = rmsnorm(x1, ln2)  (fp16)
    rmsnorm_kernel<<<MTOT, 256>>>(x1_, ln2_w, h_);

    // 9. ff = silu(h2 @ w1^T)   [16384, 2048] fp16
    gemm_hf<2, false, false, fp16><<<dim3(2 * NC / 128, MTOT / 128, 1), 256, SMEM>>>(
        h_, NC, 0, w1h, NC, 0, ff_, 2 * NC, 0, nullptr, 0, NC, 0.f);

    // 10. out = x1 + ff @ w2^T  (fp32 out)
    gemm_hf<3, false, false, float><<<dim3(NC / 128, MTOT / 128, 1), 256, SMEM>>>(
        ff_, 2 * NC, 0, w2h, 2 * NC, 0, out, NC, 0, x1_, 0, 2 * NC, 0.f);
}

// round 7
// speedup vs baseline: 7.7159x; 1.0899x over previous
#include <cuda_runtime.h>
#include <cuda_fp16.h>
#include <cstdint>
#include <math.h>

#define NB 8
#define NT 2048
#define NC 1024
#define MTOT (NB * NT)
#define EPSV 1e-6f

typedef __half fp16;
typedef __half2 fp162;

// ---------------------------------------------------------------------------
// Scratch (device globals)
// ---------------------------------------------------------------------------
__device__ __align__(16) fp16  g_h  [(size_t)MTOT * NC];
__device__ __align__(16) fp16  g_qkv[(size_t)MTOT * 3 * NC];
__device__ __align__(16) fp16  g_vt [(size_t)MTOT * NC];     // V^T per batch [C][T]
__device__ __align__(16) fp16  g_sc [(size_t)NB * NT * NT];  // scores / attn
__device__ __align__(16) fp16  g_av [(size_t)MTOT * NC];
__device__ __align__(16) float g_x1 [(size_t)MTOT * NC];     // residual stream (fp32)
__device__ __align__(16) fp16  g_ff [(size_t)MTOT * 2 * NC];
__device__ __align__(16) fp16  g_wh [(size_t)8 * NC * NC];   // fp16 weights

// ---------------------------------------------------------------------------
// Helpers
// ---------------------------------------------------------------------------
__device__ __forceinline__ uint32_t smem_u32(const void* p) {
    uint32_t a;
    asm("{ .reg .u64 t; cvta.to.shared.u64 t, %1; cvt.u32.u64 %0, t; }"
        : "=r"(a) : "l"(p));
    return a;
}
__device__ __forceinline__ void cp_async16(uint32_t dst_smem, const void* src) {
    asm volatile("cp.async.cg.shared.global [%0], [%1], 16;"
                 :: "r"(dst_smem), "l"(src) : "memory");
}
__device__ __forceinline__ void cp_commit() {
    asm volatile("cp.async.commit_group;" ::: "memory");
}
template<int N>
__device__ __forceinline__ void cp_wait() {
    asm volatile("cp.async.wait_group %0;" :: "n"(N) : "memory");
}
__device__ __forceinline__ void ldm_x4(uint32_t* r, uint32_t addr) {
    asm volatile("ldmatrix.sync.aligned.m8n8.x4.shared.b16 {%0,%1,%2,%3}, [%4];"
                 : "=r"(r[0]), "=r"(r[1]), "=r"(r[2]), "=r"(r[3]) : "r"(addr));
}
__device__ __forceinline__ void mma_f16(float* c, const uint32_t* a, const uint32_t* b) {
    asm volatile(
        "mma.sync.aligned.m16n8k16.row.col.f32.f16.f16.f32 "
        "{%0,%1,%2,%3}, {%4,%5,%6,%7}, {%8,%9}, {%0,%1,%2,%3};"
        : "+f"(c[0]), "+f"(c[1]), "+f"(c[2]), "+f"(c[3])
        : "r"(a[0]), "r"(a[1]), "r"(a[2]), "r"(a[3]), "r"(b[0]), "r"(b[1]));
}

// ---------------------------------------------------------------------------
// fp16 mma.sync GEMM:  C[M,N] = A[M,K] @ B[N,K]^T  (A,B fp16 K-major)
// CTA 128x128x64(elems), 256 threads, warp 64x32, 3-stage cp.async pipeline,
// ldmatrix fragment loads.
// EPI: 0=plain, 1=*alpha, 2=silu, 3=+residual(fp32)
// TC:  output type (fp16 or float)
// ---------------------------------------------------------------------------
template<int EPI, bool CSKIP, bool KCLIP, typename TC>
__global__ __launch_bounds__(256, 2) void gemm_hf(
    const fp16* __restrict__ A, int lda, long long sA,
    const fp16* __restrict__ B, int ldb, long long sB,
    TC* __restrict__ C, int ldc, long long sC,
    const float* __restrict__ R, long long sR,
    int K, float alpha)
{
    constexpr int BM = 128, BK = 64;               // BK in elements (128 bytes)
    constexpr int TILE = BM * 128;                 // 16 KB per operand per stage
    constexpr int STAGE = 2 * TILE;                // 32 KB
    constexpr int S = 3;

    int rm = blockIdx.y * BM;
    int cn = blockIdx.x * BM;
    if (CSKIP && cn > rm) return;
    long long z = blockIdx.z;
    A += z * sA; B += z * sB; C += z * sC;
    if (EPI == 3) R += z * sR;

    int kend = KCLIP ? min(K, rm + BM) : K;
    int nk = kend / BK;

    extern __shared__ char smem[];                 // 3 * 32 KB
    uint32_t smem_base = smem_u32(smem);

    int tid  = threadIdx.x;
    int lane = tid & 31;
    int warp = tid >> 5;
    int wm0 = (warp & 1) * 64;
    int wn0 = (warp >> 1) * 32;
    int grp = lane >> 2;
    int q   = lane & 3;

    // producer: 4 x 16B chunks per thread per operand tile (128 rows x 128B)
    int prow[4], psts[4];
    #pragma unroll
    for (int t = 0; t < 4; t++) {
        int id = tid + t * 256;
        int row = id >> 3, g = id & 7;
        prow[t] = row;
        psts[t] = row * 128 + ((g * 16) ^ ((row & 7) << 4));
    }
    const int pg = (tid & 7) * 8;                  // element offset within k-block

    // ldmatrix lane mapping (offsets within a stage's operand tile)
    // A: lanes 0-15 -> rows (kgrp 0), lanes 16-31 -> rows (kgrp 1)
    //    regs = {(r,k0),(r+8,k0),(r,k8),(r+8,k8)}
    const int la   = lane & 15;
    const int kga  = (lane >> 4) * 16;             // k-group byte offset
    const int aswz = (la & 7) << 4;
    const uint32_t a_lane_off = (uint32_t)((wm0 + la) * 128);
    // B: lanes 0-7 tile j k0 | 8-15 tile j k8 | 16-23 tile j+1 k0 | 24-31 tile j+1 k8
    //    regs = {(j,k0),(j,k8),(j+1,k0),(j+1,k8)}
    const int lb   = lane & 7;
    const int kgb  = ((lane >> 3) & 1) * 16;
    const int nofs = ((lane >> 4) & 1) * 8;
    const int bswz = lb << 4;
    const uint32_t b_lane_off = (uint32_t)(TILE + (wn0 + nofs + lb) * 128);

    float c[4][4][4];
    #pragma unroll
    for (int i = 0; i < 4; i++)
        #pragma unroll
        for (int j = 0; j < 4; j++)
            #pragma unroll
            for (int e = 0; e < 4; e++) c[i][j][e] = 0.f;

    #pragma unroll
    for (int s = 0; s < S - 1; s++) {
        if (s < nk) {
            uint32_t sa = smem_base + s * STAGE;
            int k0 = s * BK + pg;
            #pragma unroll
            for (int t = 0; t < 4; t++) {
                cp_async16(sa + psts[t],        &A[(long long)(rm + prow[t]) * lda + k0]);
                cp_async16(sa + TILE + psts[t], &B[(long long)(cn + prow[t]) * ldb + k0]);
            }
        }
        cp_commit();
    }

    for (int ki = 0; ki < nk; ki++) {
        cp_wait<S - 2>();
        __syncthreads();

        if (ki + S - 1 < nk) {
            int kn = ki + S - 1;
            uint32_t sa = smem_base + (kn % S) * STAGE;
            int k0 = kn * BK + pg;
            #pragma unroll
            for (int t = 0; t < 4; t++) {
                cp_async16(sa + psts[t],        &A[(long long)(rm + prow[t]) * lda + k0]);
                cp_async16(sa + TILE + psts[t], &B[(long long)(cn + prow[t]) * ldb + k0]);
            }
        }
        cp_commit();

        uint32_t st = smem_base + (ki % S) * STAGE;
        uint32_t abase = st + a_lane_off;
        uint32_t bbase = st + b_lane_off;
        #pragma unroll
        for (int ks = 0; ks < 4; ks++) {           // 4 x k16 = 64 elements
            int koa = (ks * 32 + kga) ^ aswz;
            int kob = (ks * 32 + kgb) ^ bswz;
            uint32_t af[4][4], bt[2][4];
            #pragma unroll
            for (int i = 0; i < 4; i++)
                ldm_x4(af[i], abase + i * 2048 + koa);
            ldm_x4(bt[0], bbase + kob);            // n-tiles 0,1
            ldm_x4(bt[1], bbase + 2048 + kob);     // n-tiles 2,3
            #pragma unroll
            for (int i = 0; i < 4; i++) {
                #pragma unroll
                for (int j = 0; j < 4; j++)
                    mma_f16(c[i][j], af[i], &bt[j >> 1][(j & 1) * 2]);
            }
        }
        __syncthreads();
    }

    // ---- epilogue ----
    #pragma unroll
    for (int i = 0; i < 4; i++) {
        int r0 = rm + wm0 + i * 16 + grp;
        #pragma unroll
        for (int j = 0; j < 4; j++) {
            int c0 = cn + wn0 + j * 8 + 2 * q;
            float v[4] = { c[i][j][0], c[i][j][1], c[i][j][2], c[i][j][3] };
            if (EPI == 1) {
                #pragma unroll
                for (int e = 0; e < 4; e++) v[e] *= alpha;
            }
            if (EPI == 2) {
                #pragma unroll
                for (int e = 0; e < 4; e++) v[e] = v[e] / (1.f + __expf(-v[e]));
            }
            if (EPI == 3) {
                float2 r0v = *(const float2*)&R[(long long)r0 * ldc + c0];
                float2 r1v = *(const float2*)&R[(long long)(r0 + 8) * ldc + c0];
                v[0] += r0v.x; v[1] += r0v.y; v[2] += r1v.x; v[3] += r1v.y;
            }
            if (sizeof(TC) == 2) {
                fp162* p0 = (fp162*)&C[(long long)r0 * ldc + c0];
                fp162* p1 = (fp162*)&C[(long long)(r0 + 8) * ldc + c0];
                *p0 = __floats2half2_rn(v[0], v[1]);
                *p1 = __floats2half2_rn(v[2], v[3]);
            } else {
                *(float2*)&C[(long long)r0 * ldc + c0]       = make_float2(v[0], v[1]);
                *(float2*)&C[(long long)(r0 + 8) * ldc + c0] = make_float2(v[2], v[3]);
            }
        }
    }
}

// ---------------------------------------------------------------------------
// Block reductions (256 threads)
// ---------------------------------------------------------------------------
__device__ __forceinline__ float block_sum(float v) {
    #pragma unroll
    for (int o = 16; o > 0; o >>= 1) v += __shfl_xor_sync(0xffffffffu, v, o);
    __shared__ float sm[8];
    if ((threadIdx.x & 31) == 0) sm[threadIdx.x >> 5] = v;
    __syncthreads();
    float r = 0.f;
    #pragma unroll
    for (int i = 0; i < 8; i++) r += sm[i];
    __syncthreads();
    return r;
}
__device__ __forceinline__ float block_max(float v) {
    #pragma unroll
    for (int o = 16; o > 0; o >>= 1) v = fmaxf(v, __shfl_xor_sync(0xffffffffu, v, o));
    __shared__ float sm[8];
    if ((threadIdx.x & 31) == 0) sm[threadIdx.x >> 5] = v;
    __syncthreads();
    float r = -1e30f;
    #pragma unroll
    for (int i = 0; i < 8; i++) r = fmaxf(r, sm[i]);
    __syncthreads();
    return r;
}

// ---------------------------------------------------------------------------
// RMSNorm: fp32 in -> fp16 out
// ---------------------------------------------------------------------------
__global__ __launch_bounds__(256) void rmsnorm_kernel(
    const float* __restrict__ x, const float* __restrict__ w, fp16* __restrict__ o)
{
    long long row = blockIdx.x;
    float4 v = ((const float4*)(x + row * NC))[threadIdx.x];
    float ss = v.x * v.x + v.y * v.y + v.z * v.z + v.w * v.w;
    ss = block_sum(ss);
    float scale = rsqrtf(ss * (1.f / NC) + EPSV);
    float4 wv = ((const float4*)w)[threadIdx.x];
    fp162 a = __floats2half2_rn(v.x * scale * wv.x, v.y * scale * wv.y);
    fp162 b = __floats2half2_rn(v.z * scale * wv.z, v.w * scale * wv.w);
    uint2 pk = make_uint2(*(uint32_t*)&a, *(uint32_t*)&b);
    ((uint2*)(o + row * NC))[threadIdx.x] = pk;
}

// ---------------------------------------------------------------------------
// Causal softmax in place (fp16 in/out, fp32 math)
// ---------------------------------------------------------------------------
__global__ __launch_bounds__(256) void softmax_kernel(fp16* __restrict__ sc)
{
    long long row = blockIdx.x;
    int t = (int)(row & (NT - 1));
    fp16* r = sc + row * NT;
    int n = t + 1;
    int base = threadIdx.x * 8;

    uint4 raw = ((const uint4*)r)[threadIdx.x];
    float v[8];
    {
        uint32_t rw[4] = { raw.x, raw.y, raw.z, raw.w };
        #pragma unroll
        for (int p = 0; p < 4; p++) {
            float2 f = __half22float2(*(fp162*)&rw[p]);
            v[2 * p] = f.x; v[2 * p + 1] = f.y;
        }
    }
    float lmax = -1e30f;
    #pragma unroll
    for (int e = 0; e < 8; e++) {
        if (base + e >= n) v[e] = -1e30f;
        lmax = fmaxf(lmax, v[e]);
    }
    float m = block_max(lmax);
    float lsum = 0.f;
    #pragma unroll
    for (int e = 0; e < 8; e++) {
        float ex = (base + e < n) ? __expf(v[e] - m) : 0.f;
        v[e] = ex;
        lsum += ex;
    }
    float s = block_sum(lsum);
    float inv = 1.f / s;
    uint32_t ow[4];
    #pragma unroll
    for (int p = 0; p < 4; p++) {
        fp162 pk = __floats2half2_rn(v[2 * p] * inv, v[2 * p + 1] * inv);
        ow[p] = *(uint32_t*)&pk;
    }
    ((uint4*)r)[threadIdx.x] = make_uint4(ow[0], ow[1], ow[2], ow[3]);
}

// ---------------------------------------------------------------------------
// Transpose V: qkv[b][s][2C..3C] -> vt[b][c][s]   (fp16)
// ---------------------------------------------------------------------------
__global__ __launch_bounds__(256) void transpose_v_kernel(
    const fp16* __restrict__ qkv, fp16* __restrict__ vt)
{
    __shared__ fp16 tile[32][34];
    int b = blockIdx.z;
    int s0 = blockIdx.x * 32, c0 = blockIdx.y * 32;
    const fp16* V = qkv + (long long)b * NT * 3 * NC + 2 * NC;
    fp16* VT = vt + (long long)b * NT * NC;
    int tx = threadIdx.x & 31, ty = threadIdx.x >> 5;
    #pragma unroll
    for (int k = 0; k < 32; k += 8)
        tile[ty + k][tx] = V[(long long)(s0 + ty + k) * (3 * NC) + c0 + tx];
    __syncthreads();
    #pragma unroll
    for (int k = 0; k < 32; k += 8)
        VT[(long long)(c0 + ty + k) * NT + s0 + tx] = tile[tx][ty + k];
}

// ---------------------------------------------------------------------------
// Weight fp32 -> fp16 conversion (8 elems/thread)
// ---------------------------------------------------------------------------
__global__ __launch_bounds__(256) void cvt_w_kernel(
    const float* __restrict__ src, fp16* __restrict__ dst)
{
    long long i = ((long long)blockIdx.x * 256 + threadIdx.x) * 8;
    float4 v0 = *(const float4*)(src + i);
    float4 v1 = *(const float4*)(src + i + 4);
    fp162 p0 = __floats2half2_rn(v0.x, v0.y);
    fp162 p1 = __floats2half2_rn(v0.z, v0.w);
    fp162 p2 = __floats2half2_rn(v1.x, v1.y);
    fp162 p3 = __floats2half2_rn(v1.z, v1.w);
    *(uint4*)(dst + i) = make_uint4(*(uint32_t*)&p0, *(uint32_t*)&p1,
                                    *(uint32_t*)&p2, *(uint32_t*)&p3);
}

// ---------------------------------------------------------------------------
// Launch sequence
// ---------------------------------------------------------------------------
extern "C" void kernel_launch(void* const* d_in, const int* in_sizes, int n_in,
                              void* d_out, int out_size)
{
    const float* x     = (const float*)d_in[0];
    const float* ln1_w = (const float*)d_in[1];
    const float* ln2_w = (const float*)d_in[2];
    const float* qkv_w = (const float*)d_in[3];
    const float* out_w = (const float*)d_in[4];
    const float* w1    = (const float*)d_in[5];
    const float* w2    = (const float*)d_in[6];
    float* out = (float*)d_out;

    fp16 *h_, *qkv_, *vt_, *sc_, *av_, *ff_, *wh_;
    float* x1_;
    cudaGetSymbolAddress((void**)&h_,   g_h);
    cudaGetSymbolAddress((void**)&qkv_, g_qkv);
    cudaGetSymbolAddress((void**)&vt_,  g_vt);
    cudaGetSymbolAddress((void**)&sc_,  g_sc);
    cudaGetSymbolAddress((void**)&av_,  g_av);
    cudaGetSymbolAddress((void**)&x1_,  g_x1);
    cudaGetSymbolAddress((void**)&ff_,  g_ff);
    cudaGetSymbolAddress((void**)&wh_,  g_wh);

    fp16* qkv_wh = wh_;                        // 3C*C
    fp16* out_wh = wh_ + (size_t)3 * NC * NC;  // C*C
    fp16* w1h    = wh_ + (size_t)4 * NC * NC;  // 2C*C
    fp16* w2h    = wh_ + (size_t)6 * NC * NC;  // 2C*C

    const long long sQKV = (long long)NT * 3 * NC;
    const long long sSC  = (long long)NT * NT;
    const long long sAV  = (long long)NT * NC;

    const int SMEM = 3 * 2 * 128 * 128;        // 96 KB

    {
        cudaFuncSetAttribute((const void*)gemm_hf<0, false, false, fp16>,
                             cudaFuncAttributeMaxDynamicSharedMemorySize, SMEM);
        cudaFuncSetAttribute((const void*)gemm_hf<1, true, false, fp16>,
                             cudaFuncAttributeMaxDynamicSharedMemorySize, SMEM);
        cudaFuncSetAttribute((const void*)gemm_hf<0, false, true, fp16>,
                             cudaFuncAttributeMaxDynamicSharedMemorySize, SMEM);
        cudaFuncSetAttribute((const void*)gemm_hf<3, false, false, float>,
                             cudaFuncAttributeMaxDynamicSharedMemorySize, SMEM);
        cudaFuncSetAttribute((const void*)gemm_hf<2, false, false, fp16>,
                             cudaFuncAttributeMaxDynamicSharedMemorySize, SMEM);
    }

    // 0. weights -> fp16
    cvt_w_kernel<<<3 * NC * NC / 2048, 256>>>(qkv_w, qkv_wh);
    cvt_w_kernel<<<NC * NC / 2048,     256>>>(out_w, out_wh);
    cvt_w_kernel<<<2 * NC * NC / 2048, 256>>>(w1, w1h);
    cvt_w_kernel<<<2 * NC * NC / 2048, 256>>>(w2, w2h);

    // 1. h = rmsnorm(x, ln1)  (fp16)
    rmsnorm_kernel<<<MTOT, 256>>>(x, ln1_w, h_);

    // 2. qkv = h @ qkv_w^T   [16384, 3072] fp16
    gemm_hf<0, false, false, fp16><<<dim3(3 * NC / 128, MTOT / 128, 1), 256, SMEM>>>(
        h_, NC, 0, qkv_wh, NC, 0, qkv_, 3 * NC, 0, nullptr, 0, NC, 0.f);

    // 3. vt = transpose(V)
    transpose_v_kernel<<<dim3(NT / 32, NC / 32, NB), 256>>>(qkv_, vt_);

    // 4. scores = (q @ k^T) / 32, causal tiles only
    gemm_hf<1, true, false, fp16><<<dim3(NT / 128, NT / 128, NB), 256, SMEM>>>(
        qkv_, 3 * NC, sQKV, qkv_ + NC, 3 * NC, sQKV,
        sc_, NT, sSC, nullptr, 0, NC, 0.03125f);

    // 5. causal softmax in place
    softmax_kernel<<<MTOT, 256>>>(sc_);

    // 6. av = attn @ vt^T (K clipped at diagonal)
    gemm_hf<0, false, true, fp16><<<dim3(NC / 128, NT / 128, NB), 256, SMEM>>>(
        sc_, NT, sSC, vt_, NT, sAV,
        av_, NC, sAV, nullptr, 0, NT, 0.f);

    // 7. x1 = x + av @ out_w^T  (fp32 out)
    gemm_hf<3, false, false, float><<<dim3(NC / 128, MTOT / 128, 1), 256, SMEM>>>(
        av_, NC, 0, out_wh, NC, 0, x1_, NC, 0, x, 0, NC, 0.f);

    // 8. h2 = rmsnorm(x1, ln2)  (fp16)
    rmsnorm_kernel<<<MTOT, 256>>>(x1_, ln2_w, h_);

    // 9. ff = silu(h2 @ w1^T)   [16384, 2048] fp16
    gemm_hf<2, false, false, fp16><<<dim3(2 * NC / 128, MTOT / 128, 1), 256, SMEM>>>(
        h_, NC, 0, w1h, NC, 0, ff_, 2 * NC, 0, nullptr, 0, NC, 0.f);

    // 10. out = x1 + ff @ w2^T  (fp32 out)
    gemm_hf<3, false, false, float><<<dim3(NC / 128, MTOT / 128, 1), 256, SMEM>>>(
        ff_, 2 * NC, 0, w2h, 2 * NC, 0, out, NC, 0, x1_, 0, 2 * NC, 0.f);
}